// round 5
// baseline (speedup 1.0000x reference)
#include <cuda_runtime.h>

// SigMMDLoss: B=4096 rows, T=4096, two input tensors (real, gen), scalar f32 out.
//
// Per-row (N = T-1 = 4095 increments dx_k = p[k+1]-p[k]):
//   f1 = sum dx            = p[N] - p[0]                        (telescoped)
//   f3 = dt*sum (k+1)dx    = p[N] - (sum_{j<N} p[j]) / N        (Abel summation)
//   f4 = sum cum(dx)*dx    = 0.5 * (f1^2 + sum dx^2)            (closed form)
//   f6 = sum dx^2
//   f8 = sum dx^3
// Time-only features cancel exactly between real/gen -> skipped.
// loss = sum_i (mean_real f_i - mean_gen f_i)^2
//
// Single fused kernel: row blocks compute features; hierarchical
// last-block-done counters perform the deterministic fp64 reduction inline
// (group reduces overlap the still-running row blocks).

#define T_LEN    4096
#define NROWS    4096
#define NBLOCKS  (2 * NROWS)
#define RT       128                  // threads per row block (4 warps)
#define WELEMS   1024                 // contiguous floats owned per warp
#define NFEAT    5
#define NGRP     64                   // reduction groups
#define GRP_SZ   (NBLOCKS / NGRP)     // 128 row-blocks per group

__device__ double g_feat[NFEAT][NBLOCKS];
__device__ double g_part[NGRP][NFEAT];
__device__ int    g_grp_ctr[NGRP];    // all self-reset each launch
__device__ int    g_ctr = 0;

// ---- packed f32x2 helpers (Blackwell; only reachable via PTX) ----
__device__ __forceinline__ unsigned long long pk2(float lo, float hi) {
    unsigned long long r;
    asm("mov.b64 %0, {%1, %2};" : "=l"(r) : "f"(lo), "f"(hi));
    return r;
}
__device__ __forceinline__ void upk2(unsigned long long p, float& lo, float& hi) {
    asm("mov.b64 {%0, %1}, %2;" : "=f"(lo), "=f"(hi) : "l"(p));
}
__device__ __forceinline__ unsigned long long fma2(unsigned long long a,
                                                   unsigned long long b,
                                                   unsigned long long c) {
    unsigned long long d;
    asm("fma.rn.f32x2 %0, %1, %2, %3;" : "=l"(d) : "l"(a), "l"(b), "l"(c));
    return d;
}
__device__ __forceinline__ unsigned long long add2(unsigned long long a,
                                                   unsigned long long b) {
    unsigned long long d;
    asm("add.rn.f32x2 %0, %1, %2;" : "=l"(d) : "l"(a), "l"(b));
    return d;
}
__device__ __forceinline__ unsigned long long mul2(unsigned long long a,
                                                   unsigned long long b) {
    unsigned long long d;
    asm("mul.rn.f32x2 %0, %1, %2;" : "=l"(d) : "l"(a), "l"(b));
    return d;
}
// fp64 warp tree reduce (deterministic)
__device__ __forceinline__ double wred(double x) {
#pragma unroll
    for (int off = 16; off; off >>= 1)
        x += __shfl_down_sync(0xffffffffu, x, off);
    return x;
}

__global__ __launch_bounds__(RT) void sigmmd_fused_kernel(
    const float* __restrict__ real_paths,
    const float* __restrict__ gen_paths,
    float* __restrict__ out)
{
    const int bid = blockIdx.x;
    const float* base = (bid < NROWS) ? real_paths : gen_paths;
    const int row = bid & (NROWS - 1);
    const float* p = base + (size_t)row * T_LEN;
    const int tid  = threadIdx.x;
    const int lane = tid & 31;
    const int w    = tid >> 5;

    __shared__ float s_w[RT / 32][3];
    __shared__ int s_flag;

    // ---- Row feature computation (warp-coalesced float4 streaming) ----
    const float4* b4 = (const float4*)p + w * (WELEMS / 4);
    float4 v[8];
#pragma unroll
    for (int i = 0; i < 8; i++) v[i] = __ldcs(b4 + i * 32 + lane);

    // Predecessor of this warp's first element (only lane 0 uses it).
    // Warp 0 lane 0: phantom dx = 0 (prev = first element itself).
    float carry = 0.f;
    if (lane == 0) carry = (w == 0) ? v[0].x : __ldcs(p + w * WELEMS - 1);

    const unsigned long long NEG1 = pk2(-1.0f, -1.0f);
    unsigned long long qp = 0ull, cp = 0ull, spp = 0ull;
#pragma unroll
    for (int i = 0; i < 8; i++) {
        float4 c4 = v[i];
        float pl = __shfl_up_sync(0xffffffffu, c4.w, 1);
        float prev = (lane == 0) ? carry : pl;
        unsigned long long cur0 = pk2(c4.x, c4.y);
        unsigned long long cur1 = pk2(c4.z, c4.w);
        unsigned long long prv0 = pk2(prev, c4.x);
        unsigned long long prv1 = pk2(c4.y, c4.z);
        unsigned long long dx0 = fma2(prv0, NEG1, cur0);   // cur - prv
        unsigned long long dx1 = fma2(prv1, NEG1, cur1);
        unsigned long long t0 = mul2(dx0, dx0);
        unsigned long long t1 = mul2(dx1, dx1);
        qp  = add2(qp, add2(t0, t1));                      // sum dx^2
        cp  = fma2(t0, dx0, cp);                           // sum dx^3
        cp  = fma2(t1, dx1, cp);
        spp = add2(spp, add2(cur0, cur1));                 // sum p
        carry = __shfl_sync(0xffffffffu, c4.w, 31);
    }
    float ql, qh, cl, ch, sl, sh;
    upk2(qp, ql, qh); upk2(cp, cl, ch); upk2(spp, sl, sh);
    float q = ql + qh, c = cl + ch, sp = sl + sh;
    if (tid == RT - 1) sp -= v[7].w;   // sum p covers p[0..N-1] only

#pragma unroll
    for (int off = 16; off; off >>= 1) {
        q  += __shfl_down_sync(0xffffffffu, q,  off);
        c  += __shfl_down_sync(0xffffffffu, c,  off);
        sp += __shfl_down_sync(0xffffffffu, sp, off);
    }
    if (lane == 0) { s_w[w][0] = q; s_w[w][1] = c; s_w[w][2] = sp; }
    __syncthreads();

    const int grp = bid / GRP_SZ;                 // 128 consecutive bids/group
    if (tid == 0) {
        double Q = 0, C = 0, SP = 0;
#pragma unroll
        for (int k = 0; k < RT / 32; k++) {
            Q  += (double)s_w[k][0];
            C  += (double)s_w[k][1];
            SP += (double)s_w[k][2];
        }
        double p0 = (double)v[0].x;
        double pN = (double)__ldg(p + T_LEN - 1);
        double S1 = pN - p0;
        g_feat[0][bid] = S1;                   // f1
        g_feat[1][bid] = pN - SP / 4095.0;     // f3
        g_feat[2][bid] = 0.5 * (S1 * S1 + Q);  // f4
        g_feat[3][bid] = Q;                    // f6
        g_feat[4][bid] = C;                    // f8
        __threadfence();
        s_flag = (atomicAdd(&g_grp_ctr[grp], 1) == GRP_SZ - 1);
    }
    __syncthreads();
    if (!s_flag) return;

    // ---- Group reduce: this block is the last of its 128-block group. ----
    // Rows [grp*128, grp*128+128) are all same-sign (4096/128 = 32 groups/tensor).
    {
        const int r = grp * GRP_SZ + tid;         // coalesced per feature plane
        double f[NFEAT];
#pragma unroll
        for (int i = 0; i < NFEAT; i++) f[i] = g_feat[i][r];
        // warp tree then cross-warp via smem (fixed order -> deterministic)
        __shared__ double s_d[RT / 32][NFEAT];
#pragma unroll
        for (int i = 0; i < NFEAT; i++) f[i] = wred(f[i]);
        if (lane == 0) {
#pragma unroll
            for (int i = 0; i < NFEAT; i++) s_d[w][i] = f[i];
        }
        __syncthreads();
        if (tid == 0) {
            const double sgn = (grp < NGRP / 2) ? 1.0 : -1.0;
#pragma unroll
            for (int i = 0; i < NFEAT; i++)
                g_part[grp][i] = sgn * (s_d[0][i] + s_d[1][i] + s_d[2][i] + s_d[3][i]);
            g_grp_ctr[grp] = 0;                   // reset for next replay
            __threadfence();
            s_flag = (atomicAdd(&g_ctr, 1) == NGRP - 1);
        }
        __syncthreads();
        if (!s_flag) return;
    }

    // ---- Final: last group standing sums 64 partials and writes the loss. ----
    if (w == 0) {                                 // one warp is enough
        double acc[NFEAT] = {0, 0, 0, 0, 0};
        if (lane < 32) {
#pragma unroll
            for (int i = 0; i < NFEAT; i++)
                acc[i] = g_part[lane][i] + g_part[lane + 32][i];
        }
#pragma unroll
        for (int i = 0; i < NFEAT; i++) acc[i] = wred(acc[i]);
        if (lane == 0) {
            double loss = 0.0;
#pragma unroll
            for (int i = 0; i < NFEAT; i++) {
                double m = acc[i] / (double)NROWS;
                loss += m * m;
            }
            out[0] = (float)loss;
            g_ctr = 0;                            // reset for next replay
        }
    }
}

extern "C" void kernel_launch(void* const* d_in, const int* in_sizes, int n_in,
                              void* d_out, int out_size)
{
    const float* real_paths = (const float*)d_in[0];
    const float* gen_paths  = (const float*)d_in[1];
    float* out = (float*)d_out;

    sigmmd_fused_kernel<<<NBLOCKS, RT>>>(real_paths, gen_paths, out);
}